// round 1
// baseline (speedup 1.0000x reference)
#include <cuda_runtime.h>
#include <math.h>

// ComplexSSMState: B=4, S=4096, G=4, D=256, N=128
// Pipeline:
//   K0a/K0b: pack complex weights into real GEMM matrices W1 (512x256), W2 (256x512)
//   K1: dt GEMV  (fp32 exact; memory-bound)
//   K2: per-(b,g) prefix sums of dt_mag/dt_phase  (cumsum(log_A) factorizes!)
//   K3: B-projection GEMM  [x_r|x_i] @ W1 -> Bx (65536x256)
//   K4/K5/K6: 3-phase segmented complex cumsum of u = Bx*dt/(cumA+1e-12), h = cumA*acc, clamp
//   K7: C-projection GEMM  [h_r|h_i] @ W2 -> y (65536x512)

#define Bb 4
#define Ss 4096
#define Gg 4
#define Dd 256
#define Nn 128
#define Mrows (Bb*Ss*Gg)     /* 65536 */
#define NCH 64
#define CH  (Ss/NCH)         /* 64 */

// ---- scratch (static device globals; no allocation allowed) ----
__device__ float g_dtm[Mrows];
__device__ float g_dtp[Mrows];
__device__ float g_Dm[Mrows];
__device__ float g_Dp[Mrows];
__device__ float g_W1[512*256];
__device__ float g_W2[256*512];
__device__ float g_Bx[16777216];   // 65536 x 256  (Bxr | Bxi)
__device__ float g_h [16777216];   // 65536 x 256  (hr  | hi )
__device__ float g_totR[16*NCH*Nn];
__device__ float g_totI[16*NCH*Nn];

// ---------------- weight packing ----------------
// W1[k][n]: Bxr = x_r B_r^T - x_i B_i^T ; Bxi = x_r B_i^T + x_i B_r^T
__global__ void pack_w1(const float* __restrict__ Bwr, const float* __restrict__ Bwi,
                        float* __restrict__ W1)
{
    int idx = blockIdx.x * 256 + threadIdx.x;   // 512*256
    int k = idx >> 8;
    int n = idx & 255;
    float v;
    if (n < 128) {
        v = (k < 256) ? Bwr[n*256 + k] : -Bwi[n*256 + (k-256)];
    } else {
        int n2 = n - 128;
        v = (k < 256) ? Bwi[n2*256 + k] : Bwr[n2*256 + (k-256)];
    }
    W1[idx] = v;
}

// W2[k][j]: yr = h_r C_r^T - h_i C_i^T ; yi = h_r C_i^T + h_i C_r^T   (C_w is (D,N) row-major)
__global__ void pack_w2(const float* __restrict__ Cwr, const float* __restrict__ Cwi,
                        float* __restrict__ W2)
{
    int idx = blockIdx.x * 256 + threadIdx.x;   // 256*512
    int k = idx >> 9;
    int j = idx & 511;
    float v;
    if (j < 256) {
        v = (k < 128) ? Cwr[j*128 + k] : -Cwi[j*128 + (k-128)];
    } else {
        int j2 = j - 256;
        v = (k < 128) ? Cwi[j2*128 + k] : Cwr[j2*128 + (k-128)];
    }
    W2[idx] = v;
}

// ---------------- dt GEMV ----------------
// one warp per token row; dt_w (2,512) staged in smem
__global__ __launch_bounds__(256)
void dt_kernel(const float* __restrict__ xr, const float* __restrict__ xi,
               const float* __restrict__ dtw, const float* __restrict__ dtb,
               float* __restrict__ dtm, float* __restrict__ dtp)
{
    __shared__ float w[1024];
    int tid = threadIdx.x;
    for (int i = tid; i < 1024; i += 256) w[i] = dtw[i];
    __syncthreads();
    int warp = tid >> 5, lane = tid & 31;
    int m = blockIdx.x * 8 + warp;
    const float* pr = xr + (size_t)m * 256;
    const float* pi = xi + (size_t)m * 256;
    float s0 = 0.f, s1 = 0.f;
    #pragma unroll
    for (int h = 0; h < 2; h++) {
        int k = h * 128 + lane * 4;
        float4 v  = *reinterpret_cast<const float4*>(pr + k);
        float4 w0 = *reinterpret_cast<const float4*>(&w[k]);
        float4 w1 = *reinterpret_cast<const float4*>(&w[512 + k]);
        s0 += v.x*w0.x + v.y*w0.y + v.z*w0.z + v.w*w0.w;
        s1 += v.x*w1.x + v.y*w1.y + v.z*w1.z + v.w*w1.w;
        float4 u  = *reinterpret_cast<const float4*>(pi + k);
        float4 a0 = *reinterpret_cast<const float4*>(&w[256 + k]);
        float4 a1 = *reinterpret_cast<const float4*>(&w[768 + k]);
        s0 += u.x*a0.x + u.y*a0.y + u.z*a0.z + u.w*a0.w;
        s1 += u.x*a1.x + u.y*a1.y + u.z*a1.z + u.w*a1.w;
    }
    #pragma unroll
    for (int o = 16; o; o >>= 1) {
        s0 += __shfl_xor_sync(0xffffffffu, s0, o);
        s1 += __shfl_xor_sync(0xffffffffu, s1, o);
    }
    if (lane == 0) {
        float m0 = fminf(fmaxf(expf(s0 + dtb[0]), 1e-4f), 2.0f);
        float m1 = fminf(fmaxf(expf(s1 + dtb[1]), 1e-4f), 2.0f);
        dtm[m] = m0; dtp[m] = m1;
    }
}

// ---------------- per-(b,g) inclusive prefix sums over S ----------------
__global__ __launch_bounds__(512)
void prefix_kernel(const float* __restrict__ dtm, const float* __restrict__ dtp,
                   float* __restrict__ Dm, float* __restrict__ Dp)
{
    int bg = blockIdx.x; int b = bg >> 2, g = bg & 3;
    int tid = threadIdx.x;
    int lane = tid & 31, warp = tid >> 5;
    float vm[8], vp[8];
    float sm = 0.f, sp = 0.f;
    int s0 = tid * 8;
    #pragma unroll
    for (int e = 0; e < 8; e++) {
        int idx = (b*Ss + s0 + e)*Gg + g;
        sm += dtm[idx]; vm[e] = sm;
        sp += dtp[idx]; vp[e] = sp;
    }
    float im = sm, ip = sp;
    #pragma unroll
    for (int o = 1; o < 32; o <<= 1) {
        float t1 = __shfl_up_sync(0xffffffffu, im, o);
        float t2 = __shfl_up_sync(0xffffffffu, ip, o);
        if (lane >= o) { im += t1; ip += t2; }
    }
    __shared__ float wm[16], wp[16];
    if (lane == 31) { wm[warp] = im; wp[warp] = ip; }
    __syncthreads();
    if (tid == 0) {
        float r = 0.f, q = 0.f;
        for (int i = 0; i < 16; i++) {
            float t1 = wm[i]; wm[i] = r; r += t1;
            float t2 = wp[i]; wp[i] = q; q += t2;
        }
    }
    __syncthreads();
    float offm = wm[warp] + (im - sm);
    float offp = wp[warp] + (ip - sp);
    #pragma unroll
    for (int e = 0; e < 8; e++) {
        int idx = (b*Ss + s0 + e)*Gg + g;
        Dm[idx] = vm[e] + offm;
        Dp[idx] = vp[e] + offp;
    }
}

// ---------------- fp32 SIMT GEMM: C[M,N] = A[M,K] @ W[K,N] ----------------
// A is split into two row-major arrays at column kSplit (for [x_r | x_i]).
// 128x128 tile, K-tile 16, 256 threads, 8x8 per thread, ping-pong smem.
__global__ __launch_bounds__(256)
void gemm_kernel(const float* __restrict__ A0, const float* __restrict__ A1,
                 int kSplit, int sA0, int sA1,
                 const float* __restrict__ W,
                 float* __restrict__ Cout, int M, int N, int K)
{
    __shared__ float As[2][16][132];
    __shared__ float Ws[2][16][128];
    int tid = threadIdx.x;
    int bm = blockIdx.y * 128;
    int bn = blockIdx.x * 128;
    int ty = tid >> 4, tx = tid & 15;
    int row0 = ty * 8, col0 = tx * 8;

    float acc[8][8];
    #pragma unroll
    for (int i = 0; i < 8; i++)
        #pragma unroll
        for (int j = 0; j < 8; j++) acc[i][j] = 0.f;

    float4 ra[2], rw[2];
    int fA = tid * 2;

    auto loadTiles = [&](int kt) {
        #pragma unroll
        for (int ii = 0; ii < 2; ii++) {
            int f = fA + ii;
            int r = f >> 2;
            int k0 = (f & 3) << 2;
            int gk = kt * 16 + k0;
            const float* p;
            if (gk < kSplit) p = A0 + (size_t)(bm + r) * sA0 + gk;
            else             p = A1 + (size_t)(bm + r) * sA1 + (gk - kSplit);
            ra[ii] = *reinterpret_cast<const float4*>(p);
            int wr = f >> 5;
            int wc = (f & 31) << 2;
            rw[ii] = *reinterpret_cast<const float4*>(W + (size_t)(kt * 16 + wr) * N + bn + wc);
        }
    };
    auto storeTiles = [&](int buf) {
        #pragma unroll
        for (int ii = 0; ii < 2; ii++) {
            int f = fA + ii;
            int r = f >> 2;
            int k0 = (f & 3) << 2;
            As[buf][k0+0][r] = ra[ii].x;
            As[buf][k0+1][r] = ra[ii].y;
            As[buf][k0+2][r] = ra[ii].z;
            As[buf][k0+3][r] = ra[ii].w;
            int wr = f >> 5;
            int wc = (f & 31) << 2;
            *reinterpret_cast<float4*>(&Ws[buf][wr][wc]) = rw[ii];
        }
    };

    loadTiles(0);
    storeTiles(0);
    __syncthreads();
    int KT = K >> 4;
    for (int kt = 0; kt < KT; kt++) {
        int cur = kt & 1;
        if (kt + 1 < KT) loadTiles(kt + 1);
        #pragma unroll
        for (int kk = 0; kk < 16; kk++) {
            float a[8], b[8];
            *reinterpret_cast<float4*>(a)     = *reinterpret_cast<const float4*>(&As[cur][kk][row0]);
            *reinterpret_cast<float4*>(a + 4) = *reinterpret_cast<const float4*>(&As[cur][kk][row0 + 4]);
            *reinterpret_cast<float4*>(b)     = *reinterpret_cast<const float4*>(&Ws[cur][kk][col0]);
            *reinterpret_cast<float4*>(b + 4) = *reinterpret_cast<const float4*>(&Ws[cur][kk][col0 + 4]);
            #pragma unroll
            for (int i = 0; i < 8; i++)
                #pragma unroll
                for (int j = 0; j < 8; j++)
                    acc[i][j] = fmaf(a[i], b[j], acc[i][j]);
        }
        if (kt + 1 < KT) storeTiles(cur ^ 1);
        __syncthreads();
    }
    #pragma unroll
    for (int i = 0; i < 8; i++) {
        size_t off = (size_t)(bm + row0 + i) * N + bn + col0;
        *reinterpret_cast<float4*>(Cout + off)     = make_float4(acc[i][0], acc[i][1], acc[i][2], acc[i][3]);
        *reinterpret_cast<float4*>(Cout + off + 4) = make_float4(acc[i][4], acc[i][5], acc[i][6], acc[i][7]);
    }
}

// ---------------- segmented complex cumsum: phase 1 (chunk totals) ----------------
__global__ __launch_bounds__(Nn)
void scan_partial_kernel(const float* __restrict__ Bx,
                         const float* __restrict__ dtm, const float* __restrict__ Dm,
                         const float* __restrict__ Dp,
                         const float* __restrict__ logAmag, const float* __restrict__ Aphase,
                         float* __restrict__ totR, float* __restrict__ totI)
{
    int n = threadIdx.x;
    int c = blockIdx.x;
    int bg = blockIdx.y;
    int b = bg >> 2, g = bg & 3;
    float nlA = -log1pf(expf(logAmag[g*Nn + n]));
    float ap  = Aphase[g*Nn + n];
    float aR = 0.f, aI = 0.f;
    int t0 = c * CH;
    for (int i = 0; i < CH; i++) {
        int m = (b*Ss + t0 + i)*Gg + g;
        float dm = Dm[m], dp = Dp[m], dt = dtm[m];
        float mag = expf(nlA * dm);
        float sn, cs; sincosf(ap * dp, &sn, &cs);
        float cr = mag * cs, ci = mag * sn;
        float dr = cr + 1e-12f, di = ci;
        float inv = 1.0f / (dr*dr + di*di);
        size_t mo = (size_t)m * 256;
        float br = Bx[mo + n] * dt;
        float bi = Bx[mo + 128 + n] * dt;
        aR += (br*dr + bi*di) * inv;
        aI += (bi*dr - br*di) * inv;
    }
    int idx = (bg*NCH + c)*Nn + n;
    totR[idx] = aR; totI[idx] = aI;
}

// phase 2: exclusive scan of chunk totals (in place)
__global__ __launch_bounds__(Nn)
void chunk_scan_kernel(float* __restrict__ totR, float* __restrict__ totI)
{
    int bg = blockIdx.x;
    int n = threadIdx.x;
    float rR = 0.f, rI = 0.f;
    for (int c = 0; c < NCH; c++) {
        int idx = (bg*NCH + c)*Nn + n;
        float tR = totR[idx], tI = totI[idx];
        totR[idx] = rR; totI[idx] = rI;
        rR += tR; rI += tI;
    }
}

// phase 3: recompute u, add offset, h = cumA * acc, clamp norm, store
__global__ __launch_bounds__(Nn)
void scan_final_kernel(const float* __restrict__ Bx,
                       const float* __restrict__ dtm, const float* __restrict__ Dm,
                       const float* __restrict__ Dp,
                       const float* __restrict__ logAmag, const float* __restrict__ Aphase,
                       const float* __restrict__ totR, const float* __restrict__ totI,
                       float* __restrict__ H)
{
    int n = threadIdx.x;
    int c = blockIdx.x;
    int bg = blockIdx.y;
    int b = bg >> 2, g = bg & 3;
    float nlA = -log1pf(expf(logAmag[g*Nn + n]));
    float ap  = Aphase[g*Nn + n];
    int idx = (bg*NCH + c)*Nn + n;
    float aR = totR[idx], aI = totI[idx];
    int t0 = c * CH;
    for (int i = 0; i < CH; i++) {
        int m = (b*Ss + t0 + i)*Gg + g;
        float dm = Dm[m], dp = Dp[m], dt = dtm[m];
        float mag = expf(nlA * dm);
        float sn, cs; sincosf(ap * dp, &sn, &cs);
        float cr = mag * cs, ci = mag * sn;
        float dr = cr + 1e-12f, di = ci;
        float inv = 1.0f / (dr*dr + di*di);
        size_t mo = (size_t)m * 256;
        float br = Bx[mo + n] * dt;
        float bi = Bx[mo + 128 + n] * dt;
        aR += (br*dr + bi*di) * inv;
        aI += (bi*dr - br*di) * inv;
        float hr = cr*aR - ci*aI;
        float hi = ci*aR + cr*aI;
        float hn = sqrtf(hr*hr + hi*hi + 1e-8f);
        float sc = fminf(hn, 100.0f) / hn;
        H[mo + n]       = hr * sc;
        H[mo + 128 + n] = hi * sc;
    }
}

// ---------------- launcher ----------------
extern "C" void kernel_launch(void* const* d_in, const int* in_sizes, int n_in,
                              void* d_out, int out_size)
{
    (void)in_sizes; (void)n_in; (void)out_size;
    const float* xr      = (const float*)d_in[0];
    const float* xi      = (const float*)d_in[1];
    const float* logAmag = (const float*)d_in[2];
    const float* Aphase  = (const float*)d_in[3];
    const float* Bwr     = (const float*)d_in[4];
    const float* Bwi     = (const float*)d_in[5];
    const float* Cwr     = (const float*)d_in[6];
    const float* Cwi     = (const float*)d_in[7];
    const float* dtw     = (const float*)d_in[8];
    const float* dtb     = (const float*)d_in[9];
    float* y = (float*)d_out;

    float *pDtm, *pDtp, *pDm, *pDp, *pW1, *pW2, *pBx, *pH, *pTR, *pTI;
    cudaGetSymbolAddress((void**)&pDtm, g_dtm);
    cudaGetSymbolAddress((void**)&pDtp, g_dtp);
    cudaGetSymbolAddress((void**)&pDm,  g_Dm);
    cudaGetSymbolAddress((void**)&pDp,  g_Dp);
    cudaGetSymbolAddress((void**)&pW1,  g_W1);
    cudaGetSymbolAddress((void**)&pW2,  g_W2);
    cudaGetSymbolAddress((void**)&pBx,  g_Bx);
    cudaGetSymbolAddress((void**)&pH,   g_h);
    cudaGetSymbolAddress((void**)&pTR,  g_totR);
    cudaGetSymbolAddress((void**)&pTI,  g_totI);

    pack_w1<<<512, 256>>>(Bwr, Bwi, pW1);
    pack_w2<<<512, 256>>>(Cwr, Cwi, pW2);
    dt_kernel<<<Mrows/8, 256>>>(xr, xi, dtw, dtb, pDtm, pDtp);
    prefix_kernel<<<16, 512>>>(pDtm, pDtp, pDm, pDp);
    // Bx = [x_r | x_i] (65536x512) @ W1 (512x256)
    gemm_kernel<<<dim3(2, Mrows/128), 256>>>(xr, xi, 256, 256, 256, pW1, pBx, Mrows, 256, 512);
    scan_partial_kernel<<<dim3(NCH, 16), Nn>>>(pBx, pDtm, pDm, pDp, logAmag, Aphase, pTR, pTI);
    chunk_scan_kernel<<<16, Nn>>>(pTR, pTI);
    scan_final_kernel<<<dim3(NCH, 16), Nn>>>(pBx, pDtm, pDm, pDp, logAmag, Aphase, pTR, pTI, pH);
    // y = [h_r | h_i] (65536x256) @ W2 (256x512)
    gemm_kernel<<<dim3(4, Mrows/128), 256>>>(pH, pH, 256, 256, 256, pW2, y, Mrows, 512, 256);
}

// round 6
// speedup vs baseline: 2.2212x; 2.2212x over previous
#include <cuda_runtime.h>
#include <stdint.h>
#include <math.h>

// ComplexSSMState: B=4, S=4096, G=4, D=256, N=128
// R5 = R3 resubmit (infra flake x3): tf32 mma.sync tensor-core GEMMs.
//   K0a/K0b: pack complex weights into real GEMM matrices W1 (512x256), W2 (256x512)
//   K1: dt GEMV  (fp32 exact)
//   K2: per-(b,g) prefix sums of dt_mag/dt_phase
//   K3: B-projection GEMM  [x_r|x_i] @ W1 -> Bx (65536x256)   [tf32 MMA]
//   K4/K5/K6: 3-phase segmented complex cumsum
//   K7: C-projection GEMM  [h_r|h_i] @ W2 -> y (65536x512)    [tf32 MMA]

#define Bb 4
#define Ss 4096
#define Gg 4
#define Dd 256
#define Nn 128
#define Mrows (Bb*Ss*Gg)     /* 65536 */
#define NCH 64
#define CH  (Ss/NCH)         /* 64 */

// ---- scratch (static device globals; no allocation allowed) ----
__device__ float g_dtm[Mrows];
__device__ float g_dtp[Mrows];
__device__ float g_Dm[Mrows];
__device__ float g_Dp[Mrows];
__device__ float g_W1[512*256];
__device__ float g_W2[256*512];
__device__ float g_Bx[16777216];   // 65536 x 256  (Bxr | Bxi)
__device__ float g_h [16777216];   // 65536 x 256  (hr  | hi )
__device__ float g_totR[16*NCH*Nn];
__device__ float g_totI[16*NCH*Nn];

// ---------------- weight packing ----------------
__global__ void pack_w1(const float* __restrict__ Bwr, const float* __restrict__ Bwi,
                        float* __restrict__ W1)
{
    int idx = blockIdx.x * 256 + threadIdx.x;   // 512*256
    int k = idx >> 8;
    int n = idx & 255;
    float v;
    if (n < 128) {
        v = (k < 256) ? Bwr[n*256 + k] : -Bwi[n*256 + (k-256)];
    } else {
        int n2 = n - 128;
        v = (k < 256) ? Bwi[n2*256 + k] : Bwr[n2*256 + (k-256)];
    }
    W1[idx] = v;
}

__global__ void pack_w2(const float* __restrict__ Cwr, const float* __restrict__ Cwi,
                        float* __restrict__ W2)
{
    int idx = blockIdx.x * 256 + threadIdx.x;   // 256*512
    int k = idx >> 9;
    int j = idx & 511;
    float v;
    if (j < 256) {
        v = (k < 128) ? Cwr[j*128 + k] : -Cwi[j*128 + (k-128)];
    } else {
        int j2 = j - 256;
        v = (k < 128) ? Cwi[j2*128 + k] : Cwr[j2*128 + (k-128)];
    }
    W2[idx] = v;
}

// ---------------- dt GEMV (fp32 exact) ----------------
__global__ __launch_bounds__(256)
void dt_kernel(const float* __restrict__ xr, const float* __restrict__ xi,
               const float* __restrict__ dtw, const float* __restrict__ dtb,
               float* __restrict__ dtm, float* __restrict__ dtp)
{
    __shared__ float w[1024];
    int tid = threadIdx.x;
    for (int i = tid; i < 1024; i += 256) w[i] = dtw[i];
    __syncthreads();
    int warp = tid >> 5, lane = tid & 31;
    int m = blockIdx.x * 8 + warp;
    const float* pr = xr + (size_t)m * 256;
    const float* pi = xi + (size_t)m * 256;
    float s0 = 0.f, s1 = 0.f;
    #pragma unroll
    for (int h = 0; h < 2; h++) {
        int k = h * 128 + lane * 4;
        float4 v  = *reinterpret_cast<const float4*>(pr + k);
        float4 w0 = *reinterpret_cast<const float4*>(&w[k]);
        float4 w1 = *reinterpret_cast<const float4*>(&w[512 + k]);
        s0 += v.x*w0.x + v.y*w0.y + v.z*w0.z + v.w*w0.w;
        s1 += v.x*w1.x + v.y*w1.y + v.z*w1.z + v.w*w1.w;
        float4 u  = *reinterpret_cast<const float4*>(pi + k);
        float4 a0 = *reinterpret_cast<const float4*>(&w[256 + k]);
        float4 a1 = *reinterpret_cast<const float4*>(&w[768 + k]);
        s0 += u.x*a0.x + u.y*a0.y + u.z*a0.z + u.w*a0.w;
        s1 += u.x*a1.x + u.y*a1.y + u.z*a1.z + u.w*a1.w;
    }
    #pragma unroll
    for (int o = 16; o; o >>= 1) {
        s0 += __shfl_xor_sync(0xffffffffu, s0, o);
        s1 += __shfl_xor_sync(0xffffffffu, s1, o);
    }
    if (lane == 0) {
        float m0 = fminf(fmaxf(expf(s0 + dtb[0]), 1e-4f), 2.0f);
        float m1 = fminf(fmaxf(expf(s1 + dtb[1]), 1e-4f), 2.0f);
        dtm[m] = m0; dtp[m] = m1;
    }
}

// ---------------- per-(b,g) inclusive prefix sums over S ----------------
__global__ __launch_bounds__(512)
void prefix_kernel(const float* __restrict__ dtm, const float* __restrict__ dtp,
                   float* __restrict__ Dm, float* __restrict__ Dp)
{
    int bg = blockIdx.x; int b = bg >> 2, g = bg & 3;
    int tid = threadIdx.x;
    int lane = tid & 31, warp = tid >> 5;
    float vm[8], vp[8];
    float sm = 0.f, sp = 0.f;
    int s0 = tid * 8;
    #pragma unroll
    for (int e = 0; e < 8; e++) {
        int idx = (b*Ss + s0 + e)*Gg + g;
        sm += dtm[idx]; vm[e] = sm;
        sp += dtp[idx]; vp[e] = sp;
    }
    float im = sm, ip = sp;
    #pragma unroll
    for (int o = 1; o < 32; o <<= 1) {
        float t1 = __shfl_up_sync(0xffffffffu, im, o);
        float t2 = __shfl_up_sync(0xffffffffu, ip, o);
        if (lane >= o) { im += t1; ip += t2; }
    }
    __shared__ float wm[16], wp[16];
    if (lane == 31) { wm[warp] = im; wp[warp] = ip; }
    __syncthreads();
    if (tid == 0) {
        float r = 0.f, q = 0.f;
        for (int i = 0; i < 16; i++) {
            float t1 = wm[i]; wm[i] = r; r += t1;
            float t2 = wp[i]; wp[i] = q; q += t2;
        }
    }
    __syncthreads();
    float offm = wm[warp] + (im - sm);
    float offp = wp[warp] + (ip - sp);
    #pragma unroll
    for (int e = 0; e < 8; e++) {
        int idx = (b*Ss + s0 + e)*Gg + g;
        Dm[idx] = vm[e] + offm;
        Dp[idx] = vp[e] + offp;
    }
}

// ---------------- tf32 tensor-core GEMM ----------------
// C[M,N] = A[M,K] @ W[K,N].  A split at kSplit across A0/A1 (both row-major).
// 128x128 CTA tile, BK=16, 256 threads = 8 warps (4 along M x 2 along N),
// warp tile 32x64 via m16n8k8 tf32 mma.sync. Double-buffered smem,
// conflict-free strides (As: 20 == 4 mod 32; Ws: 136 == 8 mod 32).

__device__ __forceinline__ uint32_t f2tf(float x) {
    uint32_t r;
    asm("cvt.rna.tf32.f32 %0, %1;" : "=r"(r) : "f"(x));
    return r;
}

__device__ __forceinline__ void mma_tf32(float c[4], const uint32_t a[4], const uint32_t b[2]) {
    asm volatile(
        "mma.sync.aligned.m16n8k8.row.col.f32.tf32.tf32.f32 "
        "{%0,%1,%2,%3}, {%4,%5,%6,%7}, {%8,%9}, {%0,%1,%2,%3};\n"
        : "+f"(c[0]), "+f"(c[1]), "+f"(c[2]), "+f"(c[3])
        : "r"(a[0]), "r"(a[1]), "r"(a[2]), "r"(a[3]), "r"(b[0]), "r"(b[1]));
}

#define GBM 128
#define GBN 128
#define GBK 16

__global__ __launch_bounds__(256, 2)
void gemm_tf32(const float* __restrict__ A0, const float* __restrict__ A1,
               int kSplit, int sA0, int sA1,
               const float* __restrict__ W,
               float* __restrict__ Cout, int M, int N, int K)
{
    __shared__ uint32_t As[2][GBM][20];
    __shared__ uint32_t Ws[2][GBK][136];

    int tid = threadIdx.x;
    int bm = blockIdx.y * GBM;
    int bn = blockIdx.x * GBN;
    int lane = tid & 31, warp = tid >> 5;
    int wm = (warp & 3) * 32;     // warp M offset
    int wn = (warp >> 2) * 64;    // warp N offset
    int gid = lane >> 2, tg = lane & 3;

    float acc[2][8][4];
    #pragma unroll
    for (int mt = 0; mt < 2; mt++)
        #pragma unroll
        for (int nt = 0; nt < 8; nt++)
            #pragma unroll
            for (int e = 0; e < 4; e++) acc[mt][nt][e] = 0.f;

    float4 ra[2], rw, rw2;

    auto loadRegs = [&](int kt) {
        #pragma unroll
        for (int i = 0; i < 2; i++) {
            int f = tid + i * 256;       // 0..511
            int r = f >> 2;              // 0..127
            int c = (f & 3) << 2;        // 0,4,8,12
            int gk = kt * GBK + c;
            const float* p = (gk < kSplit)
                ? A0 + (size_t)(bm + r) * sA0 + gk
                : A1 + (size_t)(bm + r) * sA1 + (gk - kSplit);
            ra[i] = *reinterpret_cast<const float4*>(p);
        }
        int r = tid >> 5;                // 0..7
        int c = (tid & 31) << 2;         // 0..124
        rw  = *reinterpret_cast<const float4*>(W + (size_t)(kt * GBK + r)     * N + bn + c);
        rw2 = *reinterpret_cast<const float4*>(W + (size_t)(kt * GBK + r + 8) * N + bn + c);
    };

    auto storeRegs = [&](int buf) {
        #pragma unroll
        for (int i = 0; i < 2; i++) {
            int f = tid + i * 256;
            int r = f >> 2;
            int c = (f & 3) << 2;
            As[buf][r][c + 0] = f2tf(ra[i].x);
            As[buf][r][c + 1] = f2tf(ra[i].y);
            As[buf][r][c + 2] = f2tf(ra[i].z);
            As[buf][r][c + 3] = f2tf(ra[i].w);
        }
        {
            int r = tid >> 5;
            int c = (tid & 31) << 2;
            Ws[buf][r][c + 0] = f2tf(rw.x);
            Ws[buf][r][c + 1] = f2tf(rw.y);
            Ws[buf][r][c + 2] = f2tf(rw.z);
            Ws[buf][r][c + 3] = f2tf(rw.w);
            Ws[buf][r + 8][c + 0] = f2tf(rw2.x);
            Ws[buf][r + 8][c + 1] = f2tf(rw2.y);
            Ws[buf][r + 8][c + 2] = f2tf(rw2.z);
            Ws[buf][r + 8][c + 3] = f2tf(rw2.w);
        }
    };

    auto compute = [&](int buf) {
        #pragma unroll
        for (int ks = 0; ks < 2; ks++) {
            int k0 = ks * 8;
            uint32_t a[2][4], b[8][2];
            #pragma unroll
            for (int mt = 0; mt < 2; mt++) {
                int r = wm + mt * 16 + gid;
                a[mt][0] = As[buf][r][k0 + tg];
                a[mt][1] = As[buf][r + 8][k0 + tg];
                a[mt][2] = As[buf][r][k0 + tg + 4];
                a[mt][3] = As[buf][r + 8][k0 + tg + 4];
            }
            #pragma unroll
            for (int nt = 0; nt < 8; nt++) {
                int col = wn + nt * 8 + gid;
                b[nt][0] = Ws[buf][k0 + tg][col];
                b[nt][1] = Ws[buf][k0 + tg + 4][col];
            }
            #pragma unroll
            for (int mt = 0; mt < 2; mt++)
                #pragma unroll
                for (int nt = 0; nt < 8; nt++)
                    mma_tf32(acc[mt][nt], a[mt], b[nt]);
        }
    };

    int KT = K / GBK;
    loadRegs(0);
    storeRegs(0);
    __syncthreads();
    for (int kt = 0; kt < KT; kt++) {
        if (kt + 1 < KT) loadRegs(kt + 1);
        compute(kt & 1);
        if (kt + 1 < KT) storeRegs((kt + 1) & 1);
        __syncthreads();
    }

    // epilogue
    #pragma unroll
    for (int mt = 0; mt < 2; mt++) {
        #pragma unroll
        for (int nt = 0; nt < 8; nt++) {
            int row = bm + wm + mt * 16 + gid;
            int col = bn + wn + nt * 8 + 2 * tg;
            *reinterpret_cast<float2*>(Cout + (size_t)row * N + col) =
                make_float2(acc[mt][nt][0], acc[mt][nt][1]);
            *reinterpret_cast<float2*>(Cout + (size_t)(row + 8) * N + col) =
                make_float2(acc[mt][nt][2], acc[mt][nt][3]);
        }
    }
}

// ---------------- segmented complex cumsum: phase 1 (chunk totals) ----------------
__global__ __launch_bounds__(Nn)
void scan_partial_kernel(const float* __restrict__ Bx,
                         const float* __restrict__ dtm, const float* __restrict__ Dm,
                         const float* __restrict__ Dp,
                         const float* __restrict__ logAmag, const float* __restrict__ Aphase,
                         float* __restrict__ totR, float* __restrict__ totI)
{
    int n = threadIdx.x;
    int c = blockIdx.x;
    int bg = blockIdx.y;
    int b = bg >> 2, g = bg & 3;
    float nlA = -log1pf(expf(logAmag[g*Nn + n]));
    float ap  = Aphase[g*Nn + n];
    float aR = 0.f, aI = 0.f;
    int t0 = c * CH;
    for (int i = 0; i < CH; i++) {
        int m = (b*Ss + t0 + i)*Gg + g;
        float dm = Dm[m], dp = Dp[m], dt = dtm[m];
        float mag = expf(nlA * dm);
        float sn, cs; sincosf(ap * dp, &sn, &cs);
        float cr = mag * cs, ci = mag * sn;
        float dr = cr + 1e-12f, di = ci;
        float inv = 1.0f / (dr*dr + di*di);
        size_t mo = (size_t)m * 256;
        float br = Bx[mo + n] * dt;
        float bi = Bx[mo + 128 + n] * dt;
        aR += (br*dr + bi*di) * inv;
        aI += (bi*dr - br*di) * inv;
    }
    int idx = (bg*NCH + c)*Nn + n;
    totR[idx] = aR; totI[idx] = aI;
}

// phase 2: exclusive scan of chunk totals (in place)
__global__ __launch_bounds__(Nn)
void chunk_scan_kernel(float* __restrict__ totR, float* __restrict__ totI)
{
    int bg = blockIdx.x;
    int n = threadIdx.x;
    float rR = 0.f, rI = 0.f;
    for (int c = 0; c < NCH; c++) {
        int idx = (bg*NCH + c)*Nn + n;
        float tR = totR[idx], tI = totI[idx];
        totR[idx] = rR; totI[idx] = rI;
        rR += tR; rI += tI;
    }
}

// phase 3: recompute u, add offset, h = cumA * acc, clamp norm, store
__global__ __launch_bounds__(Nn)
void scan_final_kernel(const float* __restrict__ Bx,
                       const float* __restrict__ dtm, const float* __restrict__ Dm,
                       const float* __restrict__ Dp,
                       const float* __restrict__ logAmag, const float* __restrict__ Aphase,
                       const float* __restrict__ totR, const float* __restrict__ totI,
                       float* __restrict__ H)
{
    int n = threadIdx.x;
    int c = blockIdx.x;
    int bg = blockIdx.y;
    int b = bg >> 2, g = bg & 3;
    float nlA = -log1pf(expf(logAmag[g*Nn + n]));
    float ap  = Aphase[g*Nn + n];
    int idx = (bg*NCH + c)*Nn + n;
    float aR = totR[idx], aI = totI[idx];
    int t0 = c * CH;
    for (int i = 0; i < CH; i++) {
        int m = (b*Ss + t0 + i)*Gg + g;
        float dm = Dm[m], dp = Dp[m], dt = dtm[m];
        float mag = expf(nlA * dm);
        float sn, cs; sincosf(ap * dp, &sn, &cs);
        float cr = mag * cs, ci = mag * sn;
        float dr = cr + 1e-12f, di = ci;
        float inv = 1.0f / (dr*dr + di*di);
        size_t mo = (size_t)m * 256;
        float br = Bx[mo + n] * dt;
        float bi = Bx[mo + 128 + n] * dt;
        aR += (br*dr + bi*di) * inv;
        aI += (bi*dr - br*di) * inv;
        float hr = cr*aR - ci*aI;
        float hi = ci*aR + cr*aI;
        float hn = sqrtf(hr*hr + hi*hi + 1e-8f);
        float sc = fminf(hn, 100.0f) / hn;
        H[mo + n]       = hr * sc;
        H[mo + 128 + n] = hi * sc;
    }
}

// ---------------- launcher ----------------
extern "C" void kernel_launch(void* const* d_in, const int* in_sizes, int n_in,
                              void* d_out, int out_size)
{
    (void)in_sizes; (void)n_in; (void)out_size;
    const float* xr      = (const float*)d_in[0];
    const float* xi      = (const float*)d_in[1];
    const float* logAmag = (const float*)d_in[2];
    const float* Aphase  = (const float*)d_in[3];
    const float* Bwr     = (const float*)d_in[4];
    const float* Bwi     = (const float*)d_in[5];
    const float* Cwr     = (const float*)d_in[6];
    const float* Cwi     = (const float*)d_in[7];
    const float* dtw     = (const float*)d_in[8];
    const float* dtb     = (const float*)d_in[9];
    float* y = (float*)d_out;

    float *pDtm, *pDtp, *pDm, *pDp, *pW1, *pW2, *pBx, *pH, *pTR, *pTI;
    cudaGetSymbolAddress((void**)&pDtm, g_dtm);
    cudaGetSymbolAddress((void**)&pDtp, g_dtp);
    cudaGetSymbolAddress((void**)&pDm,  g_Dm);
    cudaGetSymbolAddress((void**)&pDp,  g_Dp);
    cudaGetSymbolAddress((void**)&pW1,  g_W1);
    cudaGetSymbolAddress((void**)&pW2,  g_W2);
    cudaGetSymbolAddress((void**)&pBx,  g_Bx);
    cudaGetSymbolAddress((void**)&pH,   g_h);
    cudaGetSymbolAddress((void**)&pTR,  g_totR);
    cudaGetSymbolAddress((void**)&pTI,  g_totI);

    pack_w1<<<512, 256>>>(Bwr, Bwi, pW1);
    pack_w2<<<512, 256>>>(Cwr, Cwi, pW2);
    dt_kernel<<<Mrows/8, 256>>>(xr, xi, dtw, dtb, pDtm, pDtp);
    prefix_kernel<<<16, 512>>>(pDtm, pDtp, pDm, pDp);
    // Bx = [x_r | x_i] (65536x512) @ W1 (512x256)
    gemm_tf32<<<dim3(2, Mrows/128), 256>>>(xr, xi, 256, 256, 256, pW1, pBx, Mrows, 256, 512);
    scan_partial_kernel<<<dim3(NCH, 16), Nn>>>(pBx, pDtm, pDm, pDp, logAmag, Aphase, pTR, pTI);
    chunk_scan_kernel<<<16, Nn>>>(pTR, pTI);
    scan_final_kernel<<<dim3(NCH, 16), Nn>>>(pBx, pDtm, pDm, pDp, logAmag, Aphase, pTR, pTI, pH);
    // y = [h_r | h_i] (65536x256) @ W2 (256x512)
    gemm_tf32<<<dim3(4, Mrows/128), 256>>>(pH, pH, 256, 256, 256, pW2, y, Mrows, 512, 256);
}